// round 1
// baseline (speedup 1.0000x reference)
#include <cuda_runtime.h>
#include <cuda_bf16.h>
#include <math.h>

// Problem constants
#define B_  2
#define S_  2048
#define D_  1024
#define H_  16
#define W_  64          // head width
#define M_  (B_ * S_)   // 4096 rows for projection GEMM

// Scratch: q,k,v in [B, H, S, W] layout (16 MB each)
__device__ float g_q[B_ * H_ * S_ * W_];
__device__ float g_k[B_ * H_ * S_ * W_];
__device__ float g_v[B_ * H_ * S_ * W_];

// ---------------------------------------------------------------------------
// Projection GEMM: Out[b,h,s,w] = sum_d X[b,s,d] * Wt[d, h*64+w] + bias[n]
// M=4096, N=1024, K=1024. Block tile 64x64, BK=16, 256 threads, 4x4 microtile.
// ---------------------------------------------------------------------------
__global__ __launch_bounds__(256) void gemm_bias_kernel(
    const float* __restrict__ X, const float* __restrict__ Wt,
    const float* __restrict__ bias, float* __restrict__ Out)
{
    const int K = D_;
    const int N = D_;
    __shared__ float As[16][65];   // [k][m], padded
    __shared__ float Bs[16][64];   // [k][n]

    const int tid = threadIdx.x;
    const int ty = tid >> 4;       // 0..15
    const int tx = tid & 15;       // 0..15
    const int m0 = blockIdx.y * 64;
    const int n0 = blockIdx.x * 64;

    float acc[4][4];
#pragma unroll
    for (int i = 0; i < 4; i++)
#pragma unroll
        for (int j = 0; j < 4; j++) acc[i][j] = 0.0f;

    for (int kk = 0; kk < K; kk += 16) {
        // Load A tile 64x16 (transposed into As[k][m])
        {
            int l = tid * 4;
            int row = l >> 4;       // 0..63
            int kc  = l & 15;       // multiple of 4
            float4 v = *(const float4*)(X + (size_t)(m0 + row) * K + kk + kc);
            As[kc + 0][row] = v.x;
            As[kc + 1][row] = v.y;
            As[kc + 2][row] = v.z;
            As[kc + 3][row] = v.w;
        }
        // Load B tile 16x64
        {
            int l = tid * 4;
            int krow = l >> 6;      // 0..15
            int nc   = l & 63;      // multiple of 4
            float4 v = *(const float4*)(Wt + (size_t)(kk + krow) * N + n0 + nc);
            *(float4*)&Bs[krow][nc] = v;
        }
        __syncthreads();

#pragma unroll
        for (int k = 0; k < 16; k++) {
            float a[4];
#pragma unroll
            for (int i = 0; i < 4; i++) a[i] = As[k][ty * 4 + i];
            float4 b4 = *(const float4*)&Bs[k][tx * 4];
            float b[4] = {b4.x, b4.y, b4.z, b4.w};
#pragma unroll
            for (int i = 0; i < 4; i++)
#pragma unroll
                for (int j = 0; j < 4; j++) acc[i][j] = fmaf(a[i], b[j], acc[i][j]);
        }
        __syncthreads();
    }

    // Epilogue: write into [B,H,S,W] layout with bias
#pragma unroll
    for (int i = 0; i < 4; i++) {
        int m = m0 + ty * 4 + i;
        int b = m >> 11;            // /2048
        int s = m & 2047;
#pragma unroll
        for (int j = 0; j < 4; j++) {
            int n = n0 + tx * 4 + j;
            int h = n >> 6;
            int w = n & 63;
            Out[(((size_t)(b * H_ + h) * S_) + s) * W_ + w] = acc[i][j] + bias[n];
        }
    }
}

// ---------------------------------------------------------------------------
// Flash attention, fp32 SIMT. BQ=64 query rows/block, key tiles of 64.
// 256 threads = 16x16; thread owns 4 rows x 4 cols (both for S-tile and O-tile).
// Rows for a given ty are covered by 16 contiguous lanes (half-warp) -> shfl
// reductions for rowmax/rowsum.
// ---------------------------------------------------------------------------
__global__ __launch_bounds__(256) void attn_kernel(float* __restrict__ Out)
{
    extern __shared__ float sm[];
    float* Qs = sm;                 // 64 x 65
    float* Ks = sm + 64 * 65;       // 64 x 65
    float* Vs = Ks + 64 * 65;       // 64 x 64
    float* Ps = Vs + 64 * 64;       // 64 x 64

    const int tid = threadIdx.x;
    const int ty = tid >> 4;
    const int tx = tid & 15;
    const int q0 = blockIdx.x * 64;
    const int h  = blockIdx.y;
    const int b  = blockIdx.z;

    const size_t head_base = (size_t)(b * H_ + h) * S_ * W_;
    const float* qb = g_q + head_base;
    const float* kb = g_k + head_base;
    const float* vb = g_v + head_base;

    // Load Q tile (scaled by 1/sqrt(64) = 0.125)
    for (int l = tid * 4; l < 64 * 64; l += 1024) {
        int r = l >> 6, c = l & 63;
        float4 v = *(const float4*)(qb + (size_t)(q0 + r) * W_ + c);
        Qs[r * 65 + c + 0] = v.x * 0.125f;
        Qs[r * 65 + c + 1] = v.y * 0.125f;
        Qs[r * 65 + c + 2] = v.z * 0.125f;
        Qs[r * 65 + c + 3] = v.w * 0.125f;
    }

    float m_i[4], l_i[4], o[4][4];
#pragma unroll
    for (int r = 0; r < 4; r++) {
        m_i[r] = -INFINITY;
        l_i[r] = 0.0f;
#pragma unroll
        for (int c = 0; c < 4; c++) o[r][c] = 0.0f;
    }

    for (int j0 = 0; j0 < S_; j0 += 64) {
        __syncthreads();   // previous iteration's PV reads done before overwrite
        // Load K and V tiles
        for (int l = tid * 4; l < 64 * 64; l += 1024) {
            int r = l >> 6, c = l & 63;
            float4 kv = *(const float4*)(kb + (size_t)(j0 + r) * W_ + c);
            Ks[r * 65 + c + 0] = kv.x;
            Ks[r * 65 + c + 1] = kv.y;
            Ks[r * 65 + c + 2] = kv.z;
            Ks[r * 65 + c + 3] = kv.w;
            float4 vv = *(const float4*)(vb + (size_t)(j0 + r) * W_ + c);
            *(float4*)&Vs[r * 64 + c] = vv;
        }
        __syncthreads();

        // Scores: sc[r][c] = sum_w Q[qr][w] * K[kc][w]
        float sc[4][4];
#pragma unroll
        for (int r = 0; r < 4; r++)
#pragma unroll
            for (int c = 0; c < 4; c++) sc[r][c] = 0.0f;

#pragma unroll 16
        for (int w = 0; w < 64; w++) {
            float a[4], bb[4];
#pragma unroll
            for (int r = 0; r < 4; r++) a[r]  = Qs[(ty * 4 + r) * 65 + w];
#pragma unroll
            for (int c = 0; c < 4; c++) bb[c] = Ks[(tx * 4 + c) * 65 + w];
#pragma unroll
            for (int r = 0; r < 4; r++)
#pragma unroll
                for (int c = 0; c < 4; c++) sc[r][c] = fmaf(a[r], bb[c], sc[r][c]);
        }

        // Online softmax
        float mt[4], rs[4], alpha[4];
#pragma unroll
        for (int r = 0; r < 4; r++) {
            float v = sc[r][0];
            v = fmaxf(v, sc[r][1]); v = fmaxf(v, sc[r][2]); v = fmaxf(v, sc[r][3]);
#pragma unroll
            for (int off = 8; off > 0; off >>= 1)
                v = fmaxf(v, __shfl_xor_sync(0xffffffffu, v, off));
            float m_new = fmaxf(m_i[r], v);
            alpha[r] = __expf(m_i[r] - m_new);
            float s = 0.0f;
#pragma unroll
            for (int c = 0; c < 4; c++) {
                float p = __expf(sc[r][c] - m_new);
                sc[r][c] = p;
                s += p;
            }
#pragma unroll
            for (int off = 8; off > 0; off >>= 1)
                s += __shfl_xor_sync(0xffffffffu, s, off);
            l_i[r] = l_i[r] * alpha[r] + s;
            m_i[r] = m_new;
            rs[r] = s;
            (void)rs;
#pragma unroll
            for (int c = 0; c < 4; c++) o[r][c] *= alpha[r];
        }

        // Stage P into smem
#pragma unroll
        for (int r = 0; r < 4; r++)
#pragma unroll
            for (int c = 0; c < 4; c++)
                Ps[(ty * 4 + r) * 64 + tx * 4 + c] = sc[r][c];
        __syncthreads();

        // O += P @ V
#pragma unroll 8
        for (int kc = 0; kc < 64; kc++) {
            float a[4];
#pragma unroll
            for (int r = 0; r < 4; r++) a[r] = Ps[(ty * 4 + r) * 64 + kc];
            float4 bv = *(const float4*)&Vs[kc * 64 + tx * 4];
#pragma unroll
            for (int r = 0; r < 4; r++) {
                o[r][0] = fmaf(a[r], bv.x, o[r][0]);
                o[r][1] = fmaf(a[r], bv.y, o[r][1]);
                o[r][2] = fmaf(a[r], bv.z, o[r][2]);
                o[r][3] = fmaf(a[r], bv.w, o[r][3]);
            }
        }
    }

    // Epilogue: Out[b, s, h*64 + w] = o / l
#pragma unroll
    for (int r = 0; r < 4; r++) {
        int s = q0 + ty * 4 + r;
        float inv = 1.0f / l_i[r];
        size_t base = ((size_t)b * S_ + s) * D_ + h * W_ + tx * 4;
#pragma unroll
        for (int c = 0; c < 4; c++)
            Out[base + c] = o[r][c] * inv;
    }
}

// ---------------------------------------------------------------------------
extern "C" void kernel_launch(void* const* d_in, const int* in_sizes, int n_in,
                              void* d_out, int out_size)
{
    const float* x  = (const float*)d_in[0];
    const float* Wq = (const float*)d_in[1];
    const float* bq = (const float*)d_in[2];
    const float* Wk = (const float*)d_in[3];
    const float* bk = (const float*)d_in[4];
    const float* Wv = (const float*)d_in[5];
    const float* bv = (const float*)d_in[6];
    float* out = (float*)d_out;

    float *pq, *pk, *pv;
    cudaGetSymbolAddress((void**)&pq, g_q);
    cudaGetSymbolAddress((void**)&pk, g_k);
    cudaGetSymbolAddress((void**)&pv, g_v);

    dim3 gemm_grid(D_ / 64, M_ / 64);   // (16, 64)
    gemm_bias_kernel<<<gemm_grid, 256>>>(x, Wq, bq, pq);
    gemm_bias_kernel<<<gemm_grid, 256>>>(x, Wk, bk, pk);
    gemm_bias_kernel<<<gemm_grid, 256>>>(x, Wv, bv, pv);

    const int attn_smem = (64 * 65 * 2 + 64 * 64 * 2) * (int)sizeof(float); // 66048
    cudaFuncSetAttribute(attn_kernel, cudaFuncAttributeMaxDynamicSharedMemorySize, attn_smem);
    dim3 attn_grid(S_ / 64, H_, B_);    // (32, 16, 2)
    attn_kernel<<<attn_grid, 256, attn_smem>>>(out);
}

// round 3
// speedup vs baseline: 2.7696x; 2.7696x over previous
#include <cuda_runtime.h>
#include <math.h>
#include <stdint.h>

#define B_  2
#define S_  2048
#define D_  1024
#define H_  16
#define W_  64
#define M_  (B_ * S_)

// Scratch: q,k,v in [B, H, S, W] layout
__device__ float g_q[B_ * H_ * S_ * W_];
__device__ float g_k[B_ * H_ * S_ * W_];
__device__ float g_v[B_ * H_ * S_ * W_];

// ---------------------------------------------------------------------------
// helpers
// ---------------------------------------------------------------------------
__device__ __forceinline__ float tf32f(float x) {
    uint32_t u;
    asm("cvt.rna.tf32.f32 %0, %1;" : "=r"(u) : "f"(x));
    return __uint_as_float(u);
}
__device__ __forceinline__ void mma_tf32(float c[4], const uint32_t a[4], const uint32_t b[2]) {
    asm volatile(
        "mma.sync.aligned.m16n8k8.row.col.f32.tf32.tf32.f32 "
        "{%0,%1,%2,%3}, {%4,%5,%6,%7}, {%8,%9}, {%0,%1,%2,%3};"
        : "+f"(c[0]), "+f"(c[1]), "+f"(c[2]), "+f"(c[3])
        : "r"(a[0]), "r"(a[1]), "r"(a[2]), "r"(a[3]), "r"(b[0]), "r"(b[1]));
}

// ---------------------------------------------------------------------------
// QKV projection GEMM via mma.sync tf32.
// CTA 128x128, BK=16, 256 threads (8 warps: 4m x 2n), warp tile 32x64.
// A smem: [k][m] stride 136 + XOR-8 swizzle on m. B smem: [k][n] same scheme.
// B operand loaded directly from W [K][N] (col-major mma B == W layout).
// ---------------------------------------------------------------------------
#define BK 16
#define AST 136
#define TBUF (BK * AST)            // floats per A (or B) buffer = 2176
#define AIDX(k, m) ((k) * AST + ((m) ^ ((((k) >> 2) & 3) << 3)))

__global__ __launch_bounds__(256) void qkv_gemm(
    const float* __restrict__ X,
    const float* __restrict__ Wq_, const float* __restrict__ Wk_, const float* __restrict__ Wv_,
    const float* __restrict__ bq, const float* __restrict__ bk, const float* __restrict__ bv,
    float* __restrict__ outq, float* __restrict__ outk, float* __restrict__ outv)
{
    extern __shared__ float smg[];   // [stage][A 2176 | B 2176] x2
    const int tid = threadIdx.x;
    const int lane = tid & 31;
    const int wid = tid >> 5;
    const int wm = wid & 3, wn = wid >> 2;
    const int lt = lane & 3, lg = lane >> 2;
    const int n0 = blockIdx.x * 128;
    const int m0 = blockIdx.y * 128;
    const int z = blockIdx.z;
    const float* W = z == 0 ? Wq_ : (z == 1 ? Wk_ : Wv_);
    const float* bias = z == 0 ? bq : (z == 1 ? bk : bv);
    float* Out = z == 0 ? outq : (z == 1 ? outk : outv);

    float acc[2][8][4];
#pragma unroll
    for (int f = 0; f < 2; f++)
#pragma unroll
        for (int nb = 0; nb < 8; nb++)
#pragma unroll
            for (int j = 0; j < 4; j++) acc[f][nb][j] = 0.0f;

    float4 ra[2], rb[2];
    const int a_row0 = tid >> 2;        // + i*64 ; rows 0..127
    const int a_kq = tid & 3;           // k quad
    const int b_kr0 = tid >> 5;         // + i*8 ; k rows 0..15
    const int b_nq = tid & 31;          // n quad

#define LDG_TILE(c)                                                                 \
    {                                                                               \
        int kk = (c) * BK;                                                          \
        _Pragma("unroll")                                                           \
        for (int i = 0; i < 2; i++) {                                               \
            ra[i] = *(const float4*)(X + (size_t)(m0 + a_row0 + i * 64) * D_ + kk + a_kq * 4); \
            rb[i] = *(const float4*)(W + (size_t)(kk + b_kr0 + i * 8) * D_ + n0 + b_nq * 4);   \
        }                                                                           \
    }

#define STS_TILE(buf)                                                               \
    {                                                                               \
        float* As = smg + (buf) * 2 * TBUF;                                         \
        float* Bs = As + TBUF;                                                      \
        _Pragma("unroll")                                                           \
        for (int i = 0; i < 2; i++) {                                               \
            int row = a_row0 + i * 64;                                              \
            float av[4] = {ra[i].x, ra[i].y, ra[i].z, ra[i].w};                     \
            _Pragma("unroll")                                                       \
            for (int j = 0; j < 4; j++) As[AIDX(a_kq * 4 + j, row)] = tf32f(av[j]); \
            int kr = b_kr0 + i * 8;                                                 \
            float4 t;                                                               \
            t.x = tf32f(rb[i].x); t.y = tf32f(rb[i].y);                             \
            t.z = tf32f(rb[i].z); t.w = tf32f(rb[i].w);                             \
            *(float4*)&Bs[kr * AST + ((b_nq * 4) ^ ((((kr) >> 2) & 3) << 3))] = t;  \
        }                                                                           \
    }

    LDG_TILE(0);
    STS_TILE(0);

    const int NITER = D_ / BK;   // 64
    for (int c = 0; c < NITER; c++) {
        __syncthreads();
        if (c + 1 < NITER) LDG_TILE(c + 1);
        const float* As = smg + (c & 1) * 2 * TBUF;
        const float* Bs = As + TBUF;
#pragma unroll
        for (int t4 = 0; t4 < 2; t4++) {
            const int k8 = t4 * 8;
            uint32_t a[2][4];
#pragma unroll
            for (int f = 0; f < 2; f++) {
                const int mb = wm * 32 + f * 16;
                a[f][0] = __float_as_uint(As[AIDX(k8 + lt, mb + lg)]);
                a[f][1] = __float_as_uint(As[AIDX(k8 + lt, mb + lg + 8)]);
                a[f][2] = __float_as_uint(As[AIDX(k8 + lt + 4, mb + lg)]);
                a[f][3] = __float_as_uint(As[AIDX(k8 + lt + 4, mb + lg + 8)]);
            }
#pragma unroll
            for (int nb = 0; nb < 8; nb++) {
                const int nbb = wn * 64 + nb * 8;
                uint32_t b[2];
                b[0] = __float_as_uint(Bs[AIDX(k8 + lt, nbb + lg)]);
                b[1] = __float_as_uint(Bs[AIDX(k8 + lt + 4, nbb + lg)]);
                mma_tf32(acc[0][nb], a[0], b);
                mma_tf32(acc[1][nb], a[1], b);
            }
        }
        if (c + 1 < NITER) STS_TILE((c + 1) & 1);
    }

    // epilogue: add bias, write [B,H,S,W]
#pragma unroll
    for (int f = 0; f < 2; f++) {
#pragma unroll
        for (int half = 0; half < 2; half++) {
            int m = m0 + wm * 32 + f * 16 + lg + half * 8;
            int b = m >> 11;
            int s = m & 2047;
#pragma unroll
            for (int nb = 0; nb < 8; nb++) {
                int n = n0 + wn * 64 + nb * 8 + lt * 2;
                int h = n >> 6, w = n & 63;
                float2 v;
                v.x = acc[f][nb][half * 2 + 0] + __ldg(&bias[n]);
                v.y = acc[f][nb][half * 2 + 1] + __ldg(&bias[n + 1]);
                *(float2*)&Out[(((size_t)(b * H_ + h) * S_) + s) * W_ + w] = v;
            }
        }
    }
}

// ---------------------------------------------------------------------------
// Flash attention via mma.sync tf32. 128 threads = 4 warps, each warp owns 16
// query rows of the CTA's 64. K-tiles of 64. Arrays stride 68 (=4 mod 32):
// all fragment LDS conflict-free.
// ---------------------------------------------------------------------------
#define TST 68
#define TSZ (64 * TST)

__global__ __launch_bounds__(128) void attn_kernel(float* __restrict__ Out)
{
    extern __shared__ float sma[];
    float* Qs = sma;             // [m][w]
    float* Ks = Qs + TSZ;        // [key][w]
    float* Vs = Ks + TSZ;        // [key][w]
    float* Ps = Vs + TSZ;        // [m][key]

    const int tid = threadIdx.x;
    const int lane = tid & 31;
    const int wid = tid >> 5;
    const int lt = lane & 3, lg = lane >> 2;
    const int mb = wid * 16;
    const int q0 = blockIdx.x * 64;
    const int h = blockIdx.y, b = blockIdx.z;

    const size_t head_base = (size_t)(b * H_ + h) * S_ * W_;
    const float* qb = g_q + head_base;
    const float* kb = g_k + head_base;
    const float* vb = g_v + head_base;

    // load Q (fold 1/8 scale, cvt tf32)
#pragma unroll
    for (int i = 0; i < 8; i++) {
        int idx = i * 128 + tid;
        int r = idx >> 4, c4 = idx & 15;
        float4 v = *(const float4*)(qb + (size_t)(q0 + r) * W_ + c4 * 4);
        float4 t;
        t.x = tf32f(v.x * 0.125f); t.y = tf32f(v.y * 0.125f);
        t.z = tf32f(v.z * 0.125f); t.w = tf32f(v.w * 0.125f);
        *(float4*)&Qs[r * TST + c4 * 4] = t;
    }

    float m0r = -INFINITY, m1r = -INFINITY, l0 = 0.0f, l1 = 0.0f;
    float oacc[8][4];
#pragma unroll
    for (int nb = 0; nb < 8; nb++)
#pragma unroll
        for (int j = 0; j < 4; j++) oacc[nb][j] = 0.0f;

    for (int j0 = 0; j0 < S_; j0 += 64) {
        __syncthreads();
#pragma unroll
        for (int i = 0; i < 8; i++) {
            int idx = i * 128 + tid;
            int r = idx >> 4, c4 = idx & 15;
            float4 kv = *(const float4*)(kb + (size_t)(j0 + r) * W_ + c4 * 4);
            float4 vv = *(const float4*)(vb + (size_t)(j0 + r) * W_ + c4 * 4);
            float4 tk, tv;
            tk.x = tf32f(kv.x); tk.y = tf32f(kv.y); tk.z = tf32f(kv.z); tk.w = tf32f(kv.w);
            tv.x = tf32f(vv.x); tv.y = tf32f(vv.y); tv.z = tf32f(vv.z); tv.w = tf32f(vv.w);
            *(float4*)&Ks[r * TST + c4 * 4] = tk;
            *(float4*)&Vs[r * TST + c4 * 4] = tv;
        }
        __syncthreads();

        // S = Q @ K^T  (per warp: 16 x 64)
        float sacc[8][4];
#pragma unroll
        for (int nb = 0; nb < 8; nb++)
#pragma unroll
            for (int j = 0; j < 4; j++) sacc[nb][j] = 0.0f;

#pragma unroll
        for (int ks = 0; ks < 8; ks++) {
            const int k8 = ks * 8;
            uint32_t a[4];
            a[0] = __float_as_uint(Qs[(mb + lg) * TST + k8 + lt]);
            a[1] = __float_as_uint(Qs[(mb + lg + 8) * TST + k8 + lt]);
            a[2] = __float_as_uint(Qs[(mb + lg) * TST + k8 + lt + 4]);
            a[3] = __float_as_uint(Qs[(mb + lg + 8) * TST + k8 + lt + 4]);
#pragma unroll
            for (int nb = 0; nb < 8; nb++) {
                uint32_t bf[2];
                bf[0] = __float_as_uint(Ks[(nb * 8 + lg) * TST + k8 + lt]);
                bf[1] = __float_as_uint(Ks[(nb * 8 + lg) * TST + k8 + lt + 4]);
                mma_tf32(sacc[nb], a, bf);
            }
        }

        // online softmax on fragments (rows r0=lg, r1=lg+8 within warp tile)
        float mx0 = -INFINITY, mx1 = -INFINITY;
#pragma unroll
        for (int nb = 0; nb < 8; nb++) {
            mx0 = fmaxf(mx0, fmaxf(sacc[nb][0], sacc[nb][1]));
            mx1 = fmaxf(mx1, fmaxf(sacc[nb][2], sacc[nb][3]));
        }
        mx0 = fmaxf(mx0, __shfl_xor_sync(0xffffffffu, mx0, 1));
        mx0 = fmaxf(mx0, __shfl_xor_sync(0xffffffffu, mx0, 2));
        mx1 = fmaxf(mx1, __shfl_xor_sync(0xffffffffu, mx1, 1));
        mx1 = fmaxf(mx1, __shfl_xor_sync(0xffffffffu, mx1, 2));

        float mn0 = fmaxf(m0r, mx0), mn1 = fmaxf(m1r, mx1);
        float al0 = __expf(m0r - mn0), al1 = __expf(m1r - mn1);
        float s0 = 0.0f, s1 = 0.0f;
#pragma unroll
        for (int nb = 0; nb < 8; nb++) {
            float p0 = __expf(sacc[nb][0] - mn0);
            float p1 = __expf(sacc[nb][1] - mn0);
            float p2 = __expf(sacc[nb][2] - mn1);
            float p3 = __expf(sacc[nb][3] - mn1);
            sacc[nb][0] = p0; sacc[nb][1] = p1; sacc[nb][2] = p2; sacc[nb][3] = p3;
            s0 += p0 + p1;
            s1 += p2 + p3;
        }
        s0 += __shfl_xor_sync(0xffffffffu, s0, 1);
        s0 += __shfl_xor_sync(0xffffffffu, s0, 2);
        s1 += __shfl_xor_sync(0xffffffffu, s1, 1);
        s1 += __shfl_xor_sync(0xffffffffu, s1, 2);
        l0 = l0 * al0 + s0;
        l1 = l1 * al1 + s1;
        m0r = mn0; m1r = mn1;
#pragma unroll
        for (int nb = 0; nb < 8; nb++) {
            oacc[nb][0] *= al0; oacc[nb][1] *= al0;
            oacc[nb][2] *= al1; oacc[nb][3] *= al1;
        }

        // stage P (tf32) into smem — warp-private rows
#pragma unroll
        for (int nb = 0; nb < 8; nb++) {
            Ps[(mb + lg) * TST + nb * 8 + lt * 2]         = tf32f(sacc[nb][0]);
            Ps[(mb + lg) * TST + nb * 8 + lt * 2 + 1]     = tf32f(sacc[nb][1]);
            Ps[(mb + lg + 8) * TST + nb * 8 + lt * 2]     = tf32f(sacc[nb][2]);
            Ps[(mb + lg + 8) * TST + nb * 8 + lt * 2 + 1] = tf32f(sacc[nb][3]);
        }
        __syncwarp();

        // O += P @ V
#pragma unroll
        for (int ks = 0; ks < 8; ks++) {
            const int k8 = ks * 8;
            uint32_t a[4];
            a[0] = __float_as_uint(Ps[(mb + lg) * TST + k8 + lt]);
            a[1] = __float_as_uint(Ps[(mb + lg + 8) * TST + k8 + lt]);
            a[2] = __float_as_uint(Ps[(mb + lg) * TST + k8 + lt + 4]);
            a[3] = __float_as_uint(Ps[(mb + lg + 8) * TST + k8 + lt + 4]);
#pragma unroll
            for (int nb = 0; nb < 8; nb++) {
                uint32_t bf[2];
                bf[0] = __float_as_uint(Vs[(k8 + lt) * TST + nb * 8 + lg]);
                bf[1] = __float_as_uint(Vs[(k8 + lt + 4) * TST + nb * 8 + lg]);
                mma_tf32(oacc[nb], a, bf);
            }
        }
    }

    // epilogue: normalize by l, write [B,S,D]
    const float inv0 = 1.0f / l0, inv1 = 1.0f / l1;
    const int r0 = q0 + mb + lg;
#pragma unroll
    for (int nb = 0; nb < 8; nb++) {
        int w = nb * 8 + lt * 2;
        float2 v0, v1;
        v0.x = oacc[nb][0] * inv0; v0.y = oacc[nb][1] * inv0;
        v1.x = oacc[nb][2] * inv1; v1.y = oacc[nb][3] * inv1;
        *(float2*)&Out[((size_t)b * S_ + r0) * D_ + h * W_ + w] = v0;
        *(float2*)&Out[((size_t)b * S_ + r0 + 8) * D_ + h * W_ + w] = v1;
    }
}

// ---------------------------------------------------------------------------
extern "C" void kernel_launch(void* const* d_in, const int* in_sizes, int n_in,
                              void* d_out, int out_size)
{
    const float* x  = (const float*)d_in[0];
    const float* Wq = (const float*)d_in[1];
    const float* bq = (const float*)d_in[2];
    const float* Wk = (const float*)d_in[3];
    const float* bk = (const float*)d_in[4];
    const float* Wv = (const float*)d_in[5];
    const float* bv = (const float*)d_in[6];
    float* out = (float*)d_out;

    float *pq, *pk, *pv;
    cudaGetSymbolAddress((void**)&pq, g_q);
    cudaGetSymbolAddress((void**)&pk, g_k);
    cudaGetSymbolAddress((void**)&pv, g_v);

    const int gemm_smem = 2 * 2 * TBUF * (int)sizeof(float);  // 34816
    dim3 ggrid(D_ / 128, M_ / 128, 3);   // (8, 32, 3)
    qkv_gemm<<<ggrid, 256, gemm_smem>>>(x, Wq, Wk, Wv, bq, bk, bv, pq, pk, pv);

    const int attn_smem = 4 * TSZ * (int)sizeof(float);       // 69632
    cudaFuncSetAttribute(attn_kernel, cudaFuncAttributeMaxDynamicSharedMemorySize, attn_smem);
    dim3 attn_grid(S_ / 64, H_, B_);     // (32, 16, 2)
    attn_kernel<<<attn_grid, 128, attn_smem>>>(out);
}